// round 9
// baseline (speedup 1.0000x reference)
#include <cuda_runtime.h>

#define BB 32
#define LL 256
#define TT 1600
#define KK 80
#define PADV -1.0e12f

// ---- scratch (static device globals; no allocation) ----
__device__ float    g_lpT[BB * TT * LL];     // lp transposed [b][t][l]
__device__ float    g_A[BB * KK * LL];       // GEMM coeffs, k-major [b][k][l]
__device__ float    g_cst[BB * LL];          // per-(b,l) constant
__device__ unsigned g_D[BB * TT * 8];        // Viterbi decision bits, 256/(b,t)
__device__ int      g_path[BB * TT];         // chronological path rows (-1 = none)

// ============================================================
// K0: from mu_logvar [B][L][80] build GEMM coeffs + constant
// ============================================================
__global__ void __launch_bounds__(256) k_prep(const float* __restrict__ mlv) {
    int warp = threadIdx.x >> 5, lane = threadIdx.x & 31;
    int row = blockIdx.x * 8 + warp;           // [0, B*L)
    int b = row >> 8, l = row & 255;
    const float* p = mlv + row * 80;

    float mu = p[lane], lv = p[40 + lane];
    float iv = expf(-lv);
    g_A[(b * KK + lane) * LL + l]      = -0.0125f * iv;
    g_A[(b * KK + 40 + lane) * LL + l] =  0.025f  * mu * iv;
    float acc = mu * mu * iv + lv;
    if (lane < 8) {
        float mu2 = p[32 + lane], lv2 = p[72 + lane];
        float iv2 = expf(-lv2);
        g_A[(b * KK + 32 + lane) * LL + l] = -0.0125f * iv2;
        g_A[(b * KK + 72 + lane) * LL + l] =  0.025f  * mu2 * iv2;
        acc += mu2 * mu2 * iv2 + lv2;
    }
#pragma unroll
    for (int o = 16; o; o >>= 1) acc += __shfl_down_sync(0xffffffffu, acc, o);
    if (!lane) g_cst[row] = -0.0125f * acc;
}

// ============================================================
// K1: lp[b,l,t] = sum_k A[b,k,l] * Z[b,k,t] + cst[b,l], Z=[z^2;z]
//   64x64 tile, 4x4 register blocking; writes lp and lpT.
// ============================================================
__global__ void __launch_bounds__(256) k_lp(const float* __restrict__ z,
                                            float* __restrict__ out_lp) {
    __shared__ float As[80][64];
    __shared__ float Zs[80][64];
    int b = blockIdx.z;
    int l0 = blockIdx.y << 6, t0 = blockIdx.x << 6;
    int tid = threadIdx.x;

    for (int i = tid; i < 80 * 64; i += 256)
        As[i >> 6][i & 63] = g_A[(b * KK + (i >> 6)) * LL + l0 + (i & 63)];
    for (int i = tid; i < 40 * 64; i += 256) {
        int c = i >> 6, t = i & 63;
        float zv = z[(b * 40 + c) * TT + t0 + t];
        Zs[c][t] = zv * zv;
        Zs[40 + c][t] = zv;
    }
    __syncthreads();

    int tx = tid & 15, ty = tid >> 4;
    float acc[4][4] = {};
#pragma unroll
    for (int k = 0; k < 80; k++) {
        float4 a  = *(const float4*)&As[k][ty << 2];
        float4 zz = *(const float4*)&Zs[k][tx << 2];
        acc[0][0] += a.x * zz.x; acc[0][1] += a.x * zz.y; acc[0][2] += a.x * zz.z; acc[0][3] += a.x * zz.w;
        acc[1][0] += a.y * zz.x; acc[1][1] += a.y * zz.y; acc[1][2] += a.y * zz.z; acc[1][3] += a.y * zz.w;
        acc[2][0] += a.z * zz.x; acc[2][1] += a.z * zz.y; acc[2][2] += a.z * zz.z; acc[2][3] += a.z * zz.w;
        acc[3][0] += a.w * zz.x; acc[3][1] += a.w * zz.y; acc[3][2] += a.w * zz.z; acc[3][3] += a.w * zz.w;
    }

    float cst[4];
#pragma unroll
    for (int i = 0; i < 4; i++) cst[i] = g_cst[b * LL + l0 + (ty << 2) + i];

#pragma unroll
    for (int i = 0; i < 4; i++) {
        int l = l0 + (ty << 2) + i;
        float4 v = make_float4(acc[i][0] + cst[i], acc[i][1] + cst[i],
                               acc[i][2] + cst[i], acc[i][3] + cst[i]);
        *(float4*)&out_lp[(size_t)(b * LL + l) * TT + t0 + (tx << 2)] = v;
    }
#pragma unroll
    for (int j = 0; j < 4; j++) {
        int t = t0 + (tx << 2) + j;
        float4 v = make_float4(acc[0][j] + cst[0], acc[1][j] + cst[1],
                               acc[2][j] + cst[2], acc[3][j] + cst[3]);
        *(float4*)&g_lpT[(size_t)(b * TT + t) * LL + l0 + (ty << 2)] = v;
    }
}

// ============================================================
// K2: fused forward DP (alpha, logaddexp) + Viterbi DP (beta, max).
//   ONE WARP PER BATCH. Lane owns l = lane*8+k (blocked). No smem,
//   no barriers: k>0 stencil is a register, k=0 via rotate-shfl
//   (which also gives the (l-1)%256 wrap needed for the D bits).
//   D bits stored as one byte per lane per column.
// ============================================================
__device__ __forceinline__ float sel8(const float* a, int k) {
    float v = a[0];
#pragma unroll
    for (int i = 1; i < 8; i++) if (i == k) v = a[i];
    return v;
}

__global__ void __launch_bounds__(32) k_dp(const int* __restrict__ tl,
                                           const int* __restrict__ ml,
                                           float* __restrict__ out_loss) {
    int b = blockIdx.x, lane = threadIdx.x;
    const float* lp = g_lpT + (size_t)b * TT * LL;
    unsigned char* Db = ((unsigned char*)g_D) + (size_t)b * TT * 32;
    int mlm1 = ml[b] - 1, tlm1 = tl[b] - 1;
    int rl = tlm1 >> 3, rk = tlm1 & 7;
    int src = (lane + 31) & 31;                 // rotate-up source lane

    float a[8], bt[8];
#pragma unroll
    for (int k = 0; k < 8; k++) { a[k] = PADV; bt[k] = PADV; }
    float lp00 = lp[0];
    if (lane == 0) { a[0] = lp00; bt[0] = lp00; }
    float rec = 0.f;
    if (mlm1 == 0 && lane == rl) rec = sel8(a, rk);

    // 8-deep lp prefetch (32B per lane per step, contiguous)
    float4 pf0[8], pf1[8];
#pragma unroll
    for (int u = 0; u < 8; u++) {
        const float4* p = (const float4*)(lp + (size_t)(1 + u) * LL + lane * 8);
        pf0[u] = p[0]; pf1[u] = p[1];
    }

    for (int t0 = 1; t0 < TT; t0 += 8) {
#pragma unroll
        for (int u = 0; u < 8; u++) {
            int t = t0 + u;
            if (t >= TT) break;                 // uniform
            float4 c0 = pf0[u], c1 = pf1[u];
            int tp = t + 8;
            if (tp < TT) {
                const float4* p = (const float4*)(lp + (size_t)tp * LL + lane * 8);
                pf0[u] = p[0]; pf1[u] = p[1];
            }
            float lpv[8] = {c0.x, c0.y, c0.z, c0.w, c1.x, c1.y, c1.z, c1.w};
            float lpe[8];
#pragma unroll
            for (int k = 0; k < 8; k++) lpe[k] = lpv[k] + 1e-7f;

            // boundary values from previous step (old registers)
            float aw = __shfl_sync(0xffffffffu, a[7], src);   // alpha[l-1], lane0: l=255 (unused wrap)
            float bw = __shfl_sync(0xffffffffu, bt[7], src);  // beta[(l-1)%256]
            float am1_0 = (lane == 0) ? PADV : aw;
            float bm1_0 = (lane == 0) ? PADV : bw;

            // D bits for column t-1 (old beta, wrap semantics)
            unsigned by = (bw    > bt[0]) ? 1u   : 0u;
            by |= (bt[0] > bt[1]) ? 2u   : 0u;
            by |= (bt[1] > bt[2]) ? 4u   : 0u;
            by |= (bt[2] > bt[3]) ? 8u   : 0u;
            by |= (bt[3] > bt[4]) ? 16u  : 0u;
            by |= (bt[4] > bt[5]) ? 32u  : 0u;
            by |= (bt[5] > bt[6]) ? 64u  : 0u;
            by |= (bt[6] > bt[7]) ? 128u : 0u;
            Db[(size_t)(t - 1) * 32 + lane] = (unsigned char)by;

            // updates, descending k so a[k-1]/bt[k-1] are still old
#pragma unroll
            for (int k = 7; k >= 0; k--) {
                float am1 = (k == 0) ? am1_0 : a[k - 1];
                float bm1 = (k == 0) ? bm1_0 : bt[k - 1];
                float mx = fmaxf(a[k], am1);
                float e  = __expf(-fabsf(a[k] - am1));
                a[k]  = mx + __logf(1.f + e) + lpe[k];
                bt[k] = fmaxf(bt[k], bm1) + lpv[k];
            }
            if (t == mlm1 && lane == rl) rec = sel8(a, rk);
        }
    }
    {   // D bits for the last column (t = TT-1)
        float bw = __shfl_sync(0xffffffffu, bt[7], src);
        unsigned by = (bw    > bt[0]) ? 1u   : 0u;
        by |= (bt[0] > bt[1]) ? 2u   : 0u;
        by |= (bt[1] > bt[2]) ? 4u   : 0u;
        by |= (bt[2] > bt[3]) ? 8u   : 0u;
        by |= (bt[3] > bt[4]) ? 16u  : 0u;
        by |= (bt[4] > bt[5]) ? 32u  : 0u;
        by |= (bt[5] > bt[6]) ? 64u  : 0u;
        by |= (bt[6] > bt[7]) ? 128u : 0u;
        Db[(size_t)(TT - 1) * 32 + lane] = (unsigned char)by;
    }
    if (lane == rl) out_loss[b] = -rec / (float)(mlm1 + 1);
}

// ============================================================
// K3: backtrace with 64-bit register windows (LDS off the chain).
//   r=-1 is absorbing and writes stop at tc<0 (reference's relu
//   clamps), so walk only k=1..ml-1 with r>=0 -> no mod wraps.
//   Dsh transposed [word][col] (padded) so chunk loads batch.
// ============================================================
__global__ void __launch_bounds__(256) k_bt(const int* __restrict__ tl,
                                            const int* __restrict__ ml) {
    extern __shared__ unsigned char s3raw[];
    const int S = 1604;                              // padded col stride
    unsigned* Dsh = (unsigned*)s3raw;                // [8][S]
    int* spath = (int*)(s3raw + 8 * S * 4);          // TT ints
    int b = blockIdx.x, tid = threadIdx.x;
    const unsigned* Dg = g_D + (size_t)b * TT * 8;
    for (int i = tid; i < TT * 8; i += 256)
        Dsh[(i & 7) * S + (i >> 3)] = Dg[i];         // transpose, pad kills conflicts
    for (int i = tid; i < TT; i += 256) spath[i] = -1;
    __syncthreads();

    if (tid == 0) {
        int mlm1v = ml[b] - 1;
        int r = tl[b] - 1;
        spath[mlm1v] = r;
        int k = 1;
        while (k <= mlm1v && r >= 0) {
            int whi = r >> 5;
            int wlo = (whi > 0) ? whi - 1 : 0;
            int basep = ((whi - 1) << 5);            // pos = r - basep in [1,63]
            int c0 = mlm1v - k;
            int nst = mlm1v - k + 1; if (nst > 32) nst = 32;
            unsigned hi[32], lo[32];
#pragma unroll
            for (int u = 0; u < 32; u++) {
                int col = c0 - u; if (col < 0) col = 0;
                hi[u] = Dsh[whi * S + col];
                lo[u] = Dsh[wlo * S + col];
            }
            bool done = false;
#pragma unroll
            for (int u = 0; u < 32; u++) {
                if (u >= nst) break;
                unsigned long long w = ((unsigned long long)hi[u] << 32) | (unsigned long long)lo[u];
                int bit = (int)((w >> (unsigned)(r - basep)) & 1ull);
                r -= bit;
                spath[c0 - u] = r;
                if (r < 0) { done = true; break; }
            }
            if (done) break;
            k += nst;
        }
    }
    __syncthreads();
    for (int i = tid; i < TT; i += 256) g_path[b * TT + i] = spath[i];
}

// ============================================================
// K4: alignment[b][t][l] = (l == path[b][t])  (warp per row)
// ============================================================
__global__ void __launch_bounds__(256) k_align(float* __restrict__ out_align) {
    int gw = (blockIdx.x * 256 + threadIdx.x) >> 5;   // = b*T + t
    int lane = threadIdx.x & 31;
    int p = g_path[gw];
    int base = lane << 3;
    float4 lo = make_float4((float)(p == base),     (float)(p == base + 1),
                            (float)(p == base + 2), (float)(p == base + 3));
    float4 hi = make_float4((float)(p == base + 4), (float)(p == base + 5),
                            (float)(p == base + 6), (float)(p == base + 7));
    float* o = out_align + ((size_t)gw << 8) + base;
    *(float4*)o       = lo;
    *(float4*)(o + 4) = hi;
}

extern "C" void kernel_launch(void* const* d_in, const int* in_sizes, int n_in,
                              void* d_out, int out_size) {
    const float* mlv = (const float*)d_in[0];
    const float* z   = (const float*)d_in[1];
    const int*   tl  = (const int*)d_in[2];
    const int*   ml  = (const int*)d_in[3];

    float* out       = (float*)d_out;
    float* out_loss  = out;                                   // [32]
    float* out_align = out + 32;                              // [32,1600,256]
    float* out_lp    = out + 32 + (size_t)BB * TT * LL;       // [32,256,1600]

    k_prep<<<(BB * LL) / 8, 256>>>(mlv);
    k_lp<<<dim3(TT / 64, LL / 64, BB), 256>>>(z, out_lp);
    k_dp<<<BB, 32>>>(tl, ml, out_loss);

    int smem_bt = 8 * 1604 * 4 + TT * 4;                      // 57728 B
    cudaFuncSetAttribute(k_bt, cudaFuncAttributeMaxDynamicSharedMemorySize, smem_bt);
    k_bt<<<BB, 256, smem_bt>>>(tl, ml);

    k_align<<<(BB * TT * 32) / 256, 256>>>(out_align);
}